// round 1
// baseline (speedup 1.0000x reference)
#include <cuda_runtime.h>

#define NB 4
#define NN 16384
#define NS 4096
#define NC 64
#define NK 32
#define NCH 67            // 3 + NC
#define R2 0.04f          // float32(0.04), matches jax weak-typed promotion

// Scratch: features transposed to [B][N][C] so each index's channels are a
// contiguous 256B row (float4-loadable, full-line L2/L1 utilization).
__device__ float g_feat_t[(size_t)NB * NN * NC];

// ---------------------------------------------------------------------------
// Kernel A: transpose features [B,C,N] -> [B,N,C]
// ---------------------------------------------------------------------------
__global__ void transpose_feat(const float* __restrict__ feat) {
    __shared__ float tile[32][33];
    int b  = blockIdx.z;
    int n0 = blockIdx.x << 5;
    int c0 = blockIdx.y << 5;
    int tx = threadIdx.x;
    int ty = threadIdx.y;
#pragma unroll
    for (int i = 0; i < 32; i += 8) {
        tile[ty + i][tx] = feat[((size_t)b * NC + (c0 + ty + i)) * NN + n0 + tx];
    }
    __syncthreads();
#pragma unroll
    for (int i = 0; i < 32; i += 8) {
        g_feat_t[((size_t)b * NN + (n0 + ty + i)) * NC + c0 + tx] = tile[tx][ty + i];
    }
}

// ---------------------------------------------------------------------------
// Kernel B: fused ball query + grouping. One warp per centroid.
//   - scan xyz in chunks of 32, ballot preserves index order, early exit
//   - lane k ends up holding idx[k]  (matches output innermost-K layout)
//   - gather: lane k reads its own index's 256B channel row (float4),
//     stores are 128B coalesced warp stores per channel
// Distance formula replicates the reference bit-pattern as closely as
// possible: d2 = (|q|^2 + |p|^2) - 2*dot, squares as rn mul/add (no FMA),
// dot as an FMA chain in k-order (GEMM-style accumulation).
// ---------------------------------------------------------------------------
__global__ __launch_bounds__(256) void ball_group(
    const float* __restrict__ xyz,
    const float* __restrict__ new_xyz,
    float* __restrict__ out)
{
    int gwarp = (blockIdx.x * 256 + threadIdx.x) >> 5;
    int lane  = threadIdx.x & 31;
    int wib   = threadIdx.x >> 5;
    int b     = gwarp >> 12;          // / NS
    int s     = gwarp & (NS - 1);     // % NS

    __shared__ int s_idx[8][NK];

    const float* q = new_xyz + ((size_t)b * NS + s) * 3;
    float cx = q[0], cy = q[1], cz = q[2];
    float sq_c = __fadd_rn(__fadd_rn(__fmul_rn(cx, cx), __fmul_rn(cy, cy)),
                           __fmul_rn(cz, cz));

    const float* xb = xyz + (size_t)b * NN * 3;

    int cnt = 0;
    for (int j0 = 0; j0 < NN && cnt < NK; j0 += 32) {
        int j = j0 + lane;
        float px = xb[j * 3 + 0];
        float py = xb[j * 3 + 1];
        float pz = xb[j * 3 + 2];
        float sq_p = __fadd_rn(__fadd_rn(__fmul_rn(px, px), __fmul_rn(py, py)),
                               __fmul_rn(pz, pz));
        float dot  = __fmaf_rn(cz, pz, __fmaf_rn(cy, py, __fmul_rn(cx, px)));
        float d2   = __fsub_rn(__fadd_rn(sq_c, sq_p), 2.0f * dot);

        unsigned mask = __ballot_sync(0xffffffffu, d2 < R2);
        int pos = cnt + __popc(mask & ((1u << lane) - 1u));
        if (((mask >> lane) & 1u) && pos < NK) {
            s_idx[wib][pos] = j;
        }
        cnt += __popc(mask);
    }
    __syncwarp();

    int stored = cnt < NK ? cnt : NK;
    int first  = (stored > 0) ? s_idx[wib][0] : 0;
    int idx    = (lane < stored) ? s_idx[wib][lane] : first;

    // grouped_xyz - centroid  (channels 0..2)
    const float* p = xb + idx * 3;
    const size_t CH_STRIDE = (size_t)NS * NK;
    size_t ob = (((size_t)b * NCH) * NS + s) * NK + lane;
    out[ob]                 = __fsub_rn(p[0], cx);
    out[ob + CH_STRIDE]     = __fsub_rn(p[1], cy);
    out[ob + 2 * CH_STRIDE] = __fsub_rn(p[2], cz);

    // grouped features (channels 3..66)
    const float* f = g_feat_t + ((size_t)b * NN + idx) * NC;
    size_t o = ob + 3 * CH_STRIDE;
#pragma unroll
    for (int cc = 0; cc < NC; cc += 4) {
        float4 v = *reinterpret_cast<const float4*>(f + cc);
        out[o] = v.x; o += CH_STRIDE;
        out[o] = v.y; o += CH_STRIDE;
        out[o] = v.z; o += CH_STRIDE;
        out[o] = v.w; o += CH_STRIDE;
    }
}

// ---------------------------------------------------------------------------
extern "C" void kernel_launch(void* const* d_in, const int* in_sizes, int n_in,
                              void* d_out, int out_size)
{
    const float* xyz      = (const float*)d_in[0];   // [B,N,3]
    const float* new_xyz  = (const float*)d_in[1];   // [B,S,3]
    const float* features = (const float*)d_in[2];   // [B,C,N]
    float* out = (float*)d_out;                      // [B,67,S,K]

    dim3 tgrid(NN / 32, NC / 32, NB);
    transpose_feat<<<tgrid, dim3(32, 8)>>>(features);

    int total_threads = NB * NS * 32;                // one warp per centroid
    ball_group<<<total_threads / 256, 256>>>(xyz, new_xyz, out);
}

// round 2
// speedup vs baseline: 1.5000x; 1.5000x over previous
#include <cuda_runtime.h>

#define NB 4
#define NN 16384
#define NS 4096
#define NC 64
#define NK 32
#define NCH 67            // 3 + NC
#define R2 0.04f          // float32(0.04)

// Scratch (device globals; no allocs allowed in kernel_launch).
__device__ float  g_feat_t[(size_t)NB * NN * NC];   // features [B,N,C]
__device__ float4 g_xyzw[(size_t)NB * NN];          // (x,y,z,|p|^2)

// ---------------------------------------------------------------------------
// Kernel P: pack xyz [B,N,3] -> float4 (x,y,z,|p|^2).
// |p|^2 uses the exact rounding order of the reference (rn mul/add, no FMA).
// ---------------------------------------------------------------------------
__global__ void pack_xyz(const float* __restrict__ xyz) {
    int i = blockIdx.x * 256 + threadIdx.x;        // 0 .. B*N-1
    float x = xyz[i * 3 + 0];
    float y = xyz[i * 3 + 1];
    float z = xyz[i * 3 + 2];
    float sq = __fadd_rn(__fadd_rn(__fmul_rn(x, x), __fmul_rn(y, y)),
                         __fmul_rn(z, z));
    g_xyzw[i] = make_float4(x, y, z, sq);
}

// ---------------------------------------------------------------------------
// Kernel A: transpose features [B,C,N] -> [B,N,C]
// ---------------------------------------------------------------------------
__global__ void transpose_feat(const float* __restrict__ feat) {
    __shared__ float tile[32][33];
    int b  = blockIdx.z;
    int n0 = blockIdx.x << 5;
    int c0 = blockIdx.y << 5;
    int tx = threadIdx.x;
    int ty = threadIdx.y;
#pragma unroll
    for (int i = 0; i < 32; i += 8) {
        tile[ty + i][tx] = feat[((size_t)b * NC + (c0 + ty + i)) * NN + n0 + tx];
    }
    __syncthreads();
#pragma unroll
    for (int i = 0; i < 32; i += 8) {
        g_feat_t[((size_t)b * NN + (n0 + ty + i)) * NC + c0 + tx] = tile[tx][ty + i];
    }
}

// ---------------------------------------------------------------------------
// Kernel B: fused ball query + grouping. One warp per centroid.
// Scan unrolled 4x: 4 independent LDG.128 in flight per iteration (MLP=4),
// then 4 ballots with prefix-popc position assignment. Early exit every 128
// points. Distance arithmetic is bit-identical to R1 (rel_err was 0.0).
// ---------------------------------------------------------------------------
__global__ __launch_bounds__(256) void ball_group(
    const float* __restrict__ xyz,
    const float* __restrict__ new_xyz,
    float* __restrict__ out)
{
    int gwarp = (blockIdx.x * 256 + threadIdx.x) >> 5;
    int lane  = threadIdx.x & 31;
    int wib   = threadIdx.x >> 5;
    int b     = gwarp >> 12;          // / NS
    int s     = gwarp & (NS - 1);     // % NS

    __shared__ int s_idx[8][NK];

    const float* q = new_xyz + ((size_t)b * NS + s) * 3;
    float cx = q[0], cy = q[1], cz = q[2];
    float sq_c = __fadd_rn(__fadd_rn(__fmul_rn(cx, cx), __fmul_rn(cy, cy)),
                           __fmul_rn(cz, cz));

    const float4* xb4 = g_xyzw + (size_t)b * NN;
    const unsigned lt = (1u << lane) - 1u;

    int cnt = 0;
    for (int j0 = 0; j0 < NN && cnt < NK; j0 += 128) {
        // 4 independent 16B loads — memory latency overlapped.
        float4 p0 = xb4[j0 + lane];
        float4 p1 = xb4[j0 + 32 + lane];
        float4 p2 = xb4[j0 + 64 + lane];
        float4 p3 = xb4[j0 + 96 + lane];

        float dot0 = __fmaf_rn(cz, p0.z, __fmaf_rn(cy, p0.y, __fmul_rn(cx, p0.x)));
        float dot1 = __fmaf_rn(cz, p1.z, __fmaf_rn(cy, p1.y, __fmul_rn(cx, p1.x)));
        float dot2 = __fmaf_rn(cz, p2.z, __fmaf_rn(cy, p2.y, __fmul_rn(cx, p2.x)));
        float dot3 = __fmaf_rn(cz, p3.z, __fmaf_rn(cy, p3.y, __fmul_rn(cx, p3.x)));

        float d0 = __fsub_rn(__fadd_rn(sq_c, p0.w), 2.0f * dot0);
        float d1 = __fsub_rn(__fadd_rn(sq_c, p1.w), 2.0f * dot1);
        float d2 = __fsub_rn(__fadd_rn(sq_c, p2.w), 2.0f * dot2);
        float d3 = __fsub_rn(__fadd_rn(sq_c, p3.w), 2.0f * dot3);

        unsigned m0 = __ballot_sync(0xffffffffu, d0 < R2);
        unsigned m1 = __ballot_sync(0xffffffffu, d1 < R2);
        unsigned m2 = __ballot_sync(0xffffffffu, d2 < R2);
        unsigned m3 = __ballot_sync(0xffffffffu, d3 < R2);

        int base0 = cnt;
        int base1 = base0 + __popc(m0);
        int base2 = base1 + __popc(m1);
        int base3 = base2 + __popc(m2);
        cnt       = base3 + __popc(m3);

        if (base0 < NK) {
            int pos = base0 + __popc(m0 & lt);
            if (((m0 >> lane) & 1u) && pos < NK) s_idx[wib][pos] = j0 + lane;
        }
        if (base1 < NK) {
            int pos = base1 + __popc(m1 & lt);
            if (((m1 >> lane) & 1u) && pos < NK) s_idx[wib][pos] = j0 + 32 + lane;
        }
        if (base2 < NK) {
            int pos = base2 + __popc(m2 & lt);
            if (((m2 >> lane) & 1u) && pos < NK) s_idx[wib][pos] = j0 + 64 + lane;
        }
        if (base3 < NK) {
            int pos = base3 + __popc(m3 & lt);
            if (((m3 >> lane) & 1u) && pos < NK) s_idx[wib][pos] = j0 + 96 + lane;
        }
    }
    __syncwarp();

    int stored = cnt < NK ? cnt : NK;
    int first  = (stored > 0) ? s_idx[wib][0] : 0;
    int idx    = (lane < stored) ? s_idx[wib][lane] : first;

    // grouped_xyz - centroid  (channels 0..2)
    float4 p = xb4[idx];
    const size_t CH_STRIDE = (size_t)NS * NK;
    size_t ob = (((size_t)b * NCH) * NS + s) * NK + lane;
    out[ob]                 = __fsub_rn(p.x, cx);
    out[ob + CH_STRIDE]     = __fsub_rn(p.y, cy);
    out[ob + 2 * CH_STRIDE] = __fsub_rn(p.z, cz);

    // grouped features (channels 3..66): lane k reads its index's 256B row.
    const float* f = g_feat_t + ((size_t)b * NN + idx) * NC;
    size_t o = ob + 3 * CH_STRIDE;
#pragma unroll
    for (int cc = 0; cc < NC; cc += 4) {
        float4 v = *reinterpret_cast<const float4*>(f + cc);
        out[o] = v.x; o += CH_STRIDE;
        out[o] = v.y; o += CH_STRIDE;
        out[o] = v.z; o += CH_STRIDE;
        out[o] = v.w; o += CH_STRIDE;
    }
}

// ---------------------------------------------------------------------------
extern "C" void kernel_launch(void* const* d_in, const int* in_sizes, int n_in,
                              void* d_out, int out_size)
{
    const float* xyz      = (const float*)d_in[0];   // [B,N,3]
    const float* new_xyz  = (const float*)d_in[1];   // [B,S,3]
    const float* features = (const float*)d_in[2];   // [B,C,N]
    float* out = (float*)d_out;                      // [B,67,S,K]

    pack_xyz<<<(NB * NN) / 256, 256>>>(xyz);

    dim3 tgrid(NN / 32, NC / 32, NB);
    transpose_feat<<<tgrid, dim3(32, 8)>>>(features);

    int total_threads = NB * NS * 32;                // one warp per centroid
    ball_group<<<total_threads / 256, 256>>>(xyz, new_xyz, out);
}

// round 3
// speedup vs baseline: 1.5289x; 1.0193x over previous
#include <cuda_runtime.h>

#define NB 4
#define NN 16384
#define NS 4096
#define NC 64
#define NK 32
#define NCH 67            // 3 + NC
#define R2 0.04f          // float32(0.04)
#define TOTAL_CENT (NB * NS)

// Scratch (device globals; no allocs allowed).
__device__ float  g_feat_t[(size_t)NB * NN * NC];   // features [B,N,C]
__device__ float4 g_xyzw[(size_t)NB * NN];          // (x,y,z,|p|^2)
__device__ int    g_ctr;                             // work-queue counter

// ---------------------------------------------------------------------------
// Prep kernel: fused  (a) xyz pack -> float4(x,y,z,|p|^2)
//                     (b) feature transpose [B,C,N] -> [B,N,C]
//                     (c) work-queue counter reset
// Block ranges: [0,256) pack, [256, 256+4096) transpose.
// ---------------------------------------------------------------------------
__global__ void prep(const float* __restrict__ xyz,
                     const float* __restrict__ feat) {
    int tx = threadIdx.x;            // 0..31
    int ty = threadIdx.y;            // 0..7
    int bid = blockIdx.x;

    if (bid == 0 && tx == 0 && ty == 0) g_ctr = 0;

    if (bid < 256) {
        // pack: 256 blocks x 256 threads = 65536 = B*N
        int i = bid * 256 + ty * 32 + tx;
        float x = xyz[i * 3 + 0];
        float y = xyz[i * 3 + 1];
        float z = xyz[i * 3 + 2];
        float sq = __fadd_rn(__fadd_rn(__fmul_rn(x, x), __fmul_rn(y, y)),
                             __fmul_rn(z, z));
        g_xyzw[i] = make_float4(x, y, z, sq);
    } else {
        // transpose: 4096 blocks; decode b / c-tile / n-tile
        int tb  = bid - 256;
        int b   = tb >> 10;
        int rem = tb & 1023;
        int c0  = (rem >> 9) << 5;   // 0 or 32
        int n0  = (rem & 511) << 5;
        __shared__ float tile[32][33];
#pragma unroll
        for (int i = 0; i < 32; i += 8) {
            tile[ty + i][tx] = feat[((size_t)b * NC + (c0 + ty + i)) * NN + n0 + tx];
        }
        __syncthreads();
#pragma unroll
        for (int i = 0; i < 32; i += 8) {
            g_feat_t[((size_t)b * NN + (n0 + ty + i)) * NC + c0 + tx] = tile[tx][ty + i];
        }
    }
}

// ---------------------------------------------------------------------------
// Fused ball query + grouping. PERSISTENT WARPS: each warp fetches centroids
// from a global atomic queue (load-balanced — scan lengths vary ~1K..16K).
// Scan unrolled 8x: 8 independent LDG.128 in flight, 8 ballots back-to-back.
// Distance arithmetic bit-identical to R1/R2 (rel_err 0.0).
// ---------------------------------------------------------------------------
__global__ __launch_bounds__(256) void ball_group(
    const float* __restrict__ new_xyz,
    float* __restrict__ out)
{
    int lane = threadIdx.x & 31;
    int wib  = threadIdx.x >> 5;
    const unsigned lt = (1u << lane) - 1u;

    __shared__ int s_idx[8][NK];

    for (;;) {
        int cent;
        if (lane == 0) cent = atomicAdd(&g_ctr, 1);
        cent = __shfl_sync(0xffffffffu, cent, 0);
        if (cent >= TOTAL_CENT) return;

        int b = cent >> 12;          // / NS
        int s = cent & (NS - 1);     // % NS

        const float* q = new_xyz + ((size_t)b * NS + s) * 3;
        float cx = q[0], cy = q[1], cz = q[2];
        float sq_c = __fadd_rn(__fadd_rn(__fmul_rn(cx, cx), __fmul_rn(cy, cy)),
                               __fmul_rn(cz, cz));

        const float4* xb4 = g_xyzw + (size_t)b * NN;

        int cnt = 0;
        for (int j0 = 0; j0 < NN && cnt < NK; j0 += 256) {
            float4 p[8];
#pragma unroll
            for (int u = 0; u < 8; u++) p[u] = xb4[j0 + u * 32 + lane];

            unsigned m[8];
#pragma unroll
            for (int u = 0; u < 8; u++) {
                float dot = __fmaf_rn(cz, p[u].z,
                            __fmaf_rn(cy, p[u].y, __fmul_rn(cx, p[u].x)));
                float d2  = __fsub_rn(__fadd_rn(sq_c, p[u].w), 2.0f * dot);
                m[u] = __ballot_sync(0xffffffffu, d2 < R2);
            }

#pragma unroll
            for (int u = 0; u < 8; u++) {
                if (cnt < NK) {
                    int pos = cnt + __popc(m[u] & lt);
                    if (((m[u] >> lane) & 1u) && pos < NK)
                        s_idx[wib][pos] = j0 + u * 32 + lane;
                }
                cnt += __popc(m[u]);
            }
        }
        __syncwarp();

        int stored = cnt < NK ? cnt : NK;
        int first  = (stored > 0) ? s_idx[wib][0] : 0;
        int idx    = (lane < stored) ? s_idx[wib][lane] : first;

        // grouped_xyz - centroid  (channels 0..2)
        float4 p = xb4[idx];
        const size_t CH_STRIDE = (size_t)NS * NK;
        size_t ob = (((size_t)b * NCH) * NS + s) * NK + lane;
        out[ob]                 = __fsub_rn(p.x, cx);
        out[ob + CH_STRIDE]     = __fsub_rn(p.y, cy);
        out[ob + 2 * CH_STRIDE] = __fsub_rn(p.z, cz);

        // grouped features (channels 3..66)
        const float* f = g_feat_t + ((size_t)b * NN + idx) * NC;
        size_t o = ob + 3 * CH_STRIDE;
#pragma unroll
        for (int cc = 0; cc < NC; cc += 4) {
            float4 v = *reinterpret_cast<const float4*>(f + cc);
            out[o] = v.x; o += CH_STRIDE;
            out[o] = v.y; o += CH_STRIDE;
            out[o] = v.z; o += CH_STRIDE;
            out[o] = v.w; o += CH_STRIDE;
        }
        __syncwarp();   // protect s_idx row before next centroid's scan
    }
}

// ---------------------------------------------------------------------------
extern "C" void kernel_launch(void* const* d_in, const int* in_sizes, int n_in,
                              void* d_out, int out_size)
{
    const float* xyz      = (const float*)d_in[0];   // [B,N,3]
    const float* new_xyz  = (const float*)d_in[1];   // [B,S,3]
    const float* features = (const float*)d_in[2];   // [B,C,N]
    float* out = (float*)d_out;                      // [B,67,S,K]

    prep<<<256 + 4096, dim3(32, 8)>>>(xyz, features);

    // persistent warps: ~8 blocks/SM * 148 SMs
    ball_group<<<1184, 256>>>(new_xyz, out);
}